// round 1
// baseline (speedup 1.0000x reference)
#include <cuda_runtime.h>

#define BMAX 16384

// Scratch (device globals — no runtime allocation)
__device__ float g_y1[BMAX * 8 * 13 * 13];  // after conv1+pool
__device__ float g_y2[BMAX * 400];          // after conv2+pool (flattened C,H,W)

// ---------------------------------------------------------------------------
// Kernel 1: conv1(3x3, 1->8) + bias + relu + maxpool2  ->  [B,8,13,13]
// One image per block. relu(max(c)+b) == max(relu(c+b)) since relu monotonic.
// ---------------------------------------------------------------------------
__global__ void __launch_bounds__(192) k1_conv1(const float* __restrict__ x,
                                                const float* __restrict__ w,
                                                const float* __restrict__ b) {
    __shared__ float sx[784];
    __shared__ float sw[72];
    __shared__ float sb[8];
    const int img = blockIdx.x;
    const float* xin = x + img * 784;
    for (int i = threadIdx.x; i < 784; i += blockDim.x) sx[i] = xin[i];
    if (threadIdx.x < 72) sw[threadIdx.x] = w[threadIdx.x];
    if (threadIdx.x < 8)  sb[threadIdx.x] = b[threadIdx.x];
    __syncthreads();

    const int t = threadIdx.x;
    if (t >= 169) return;
    const int py = t / 13, px = t % 13;

    // 4x4 input window covering the 2x2 pool region's 3x3 convs
    float win[4][4];
#pragma unroll
    for (int i = 0; i < 4; i++)
#pragma unroll
        for (int j = 0; j < 4; j++)
            win[i][j] = sx[(2 * py + i) * 28 + (2 * px + j)];

    float* out = g_y1 + img * 1352;  // 8*169
#pragma unroll
    for (int oc = 0; oc < 8; oc++) {
        float c00 = 0.f, c01 = 0.f, c10 = 0.f, c11 = 0.f;
#pragma unroll
        for (int ky = 0; ky < 3; ky++)
#pragma unroll
            for (int kx = 0; kx < 3; kx++) {
                const float wv = sw[oc * 9 + ky * 3 + kx];
                c00 = fmaf(win[ky][kx],         wv, c00);
                c01 = fmaf(win[ky][kx + 1],     wv, c01);
                c10 = fmaf(win[ky + 1][kx],     wv, c10);
                c11 = fmaf(win[ky + 1][kx + 1], wv, c11);
            }
        float m = fmaxf(fmaxf(c00, c01), fmaxf(c10, c11)) + sb[oc];
        out[oc * 169 + t] = fmaxf(m, 0.f);
    }
}

// ---------------------------------------------------------------------------
// Kernel 2: conv2(3x3, 8->16) + bias + relu + maxpool2 -> [B,400] flat (C,H,W)
// One image per block, 400 threads = 16 oc * 25 positions.
// ---------------------------------------------------------------------------
__global__ void __launch_bounds__(400) k2_conv2(const float* __restrict__ w,
                                                const float* __restrict__ b) {
    __shared__ float sin[8 * 169];
    __shared__ float sw[16 * 72];
    __shared__ float sb[16];
    const int img = blockIdx.x;
    const float* yin = g_y1 + img * 1352;
    for (int i = threadIdx.x; i < 1352; i += blockDim.x) sin[i] = yin[i];
    for (int i = threadIdx.x; i < 1152; i += blockDim.x) sw[i] = w[i];
    if (threadIdx.x < 16) sb[threadIdx.x] = b[threadIdx.x];
    __syncthreads();

    const int t = threadIdx.x;  // t = oc*25 + pos, exactly the flat output idx
    const int oc = t / 25, pos = t % 25;
    const int py = pos / 5, px = pos % 5;

    float c00 = 0.f, c01 = 0.f, c10 = 0.f, c11 = 0.f;
#pragma unroll
    for (int ic = 0; ic < 8; ic++) {
        const float* inp = sin + ic * 169 + (2 * py) * 13 + 2 * px;
        float win[4][4];
#pragma unroll
        for (int i = 0; i < 4; i++)
#pragma unroll
            for (int j = 0; j < 4; j++)
                win[i][j] = inp[i * 13 + j];
        const float* wp = sw + (oc * 8 + ic) * 9;
#pragma unroll
        for (int ky = 0; ky < 3; ky++)
#pragma unroll
            for (int kx = 0; kx < 3; kx++) {
                const float wv = wp[ky * 3 + kx];
                c00 = fmaf(win[ky][kx],         wv, c00);
                c01 = fmaf(win[ky][kx + 1],     wv, c01);
                c10 = fmaf(win[ky + 1][kx],     wv, c10);
                c11 = fmaf(win[ky + 1][kx + 1], wv, c11);
            }
    }
    float m = fmaxf(fmaxf(c00, c01), fmaxf(c10, c11)) + sb[oc];
    g_y2[img * 400 + t] = fmaxf(m, 0.f);
}

// ---------------------------------------------------------------------------
// Kernel 3: fc1(400->128)+relu, fc2(128->64), fc3(64->10), 16 rows per block.
// ---------------------------------------------------------------------------
__global__ void __launch_bounds__(128) k3_fc(const float* __restrict__ fc_w,
                                             const float* __restrict__ fc_b,
                                             const float* __restrict__ fc2_w,
                                             const float* __restrict__ fc2_b,
                                             const float* __restrict__ fc3_w,
                                             const float* __restrict__ fc3_b,
                                             float* __restrict__ out) {
    __shared__ float4 sx[16 * 100];   // 25.6 KB : X tile [16][400]
    __shared__ float4 sh1[16 * 32];   //  8.0 KB : h1 tile [16][128]
    __shared__ float  sh2[16 * 64];   //  4.0 KB : h2 tile [16][64]
    __shared__ float  sw3[640];
    __shared__ float  sb3[10];

    const int r0 = blockIdx.x * 16;
    const int t = threadIdx.x;

    const float4* xin = (const float4*)(g_y2 + r0 * 400);
    for (int i = t; i < 1600; i += 128) sx[i] = xin[i];
    for (int i = t; i < 640; i += 128) sw3[i] = fc3_w[i];
    if (t < 10) sb3[t] = fc3_b[t];
    __syncthreads();

    // ---- stage 1: h1[r][t] = relu(X[r] . fc_w[t] + fc_b[t]) ----
    {
        float acc[16];
#pragma unroll
        for (int r = 0; r < 16; r++) acc[r] = 0.f;
        const float4* wp = (const float4*)(fc_w + t * 400);
#pragma unroll 2
        for (int k4 = 0; k4 < 100; k4++) {
            const float4 w4 = wp[k4];
#pragma unroll
            for (int r = 0; r < 16; r++) {
                const float4 x4 = sx[r * 100 + k4];
                acc[r] = fmaf(x4.x, w4.x, acc[r]);
                acc[r] = fmaf(x4.y, w4.y, acc[r]);
                acc[r] = fmaf(x4.z, w4.z, acc[r]);
                acc[r] = fmaf(x4.w, w4.w, acc[r]);
            }
        }
        const float bb = fc_b[t];
        float* h1f = (float*)sh1;
#pragma unroll
        for (int r = 0; r < 16; r++)
            h1f[r * 128 + t] = fmaxf(acc[r] + bb, 0.f);
    }
    __syncthreads();

    // ---- stage 2: h2[r][c] = h1[r] . fc2_w[c] + fc2_b[c] ----
    {
        const int c = t & 63;
        const int rbase = (t >> 6) * 8;
        float acc[8];
#pragma unroll
        for (int r = 0; r < 8; r++) acc[r] = 0.f;
        const float4* wp = (const float4*)(fc2_w + c * 128);
#pragma unroll 4
        for (int k4 = 0; k4 < 32; k4++) {
            const float4 w4 = wp[k4];
#pragma unroll
            for (int r = 0; r < 8; r++) {
                const float4 h4 = sh1[(rbase + r) * 32 + k4];
                acc[r] = fmaf(h4.x, w4.x, acc[r]);
                acc[r] = fmaf(h4.y, w4.y, acc[r]);
                acc[r] = fmaf(h4.z, w4.z, acc[r]);
                acc[r] = fmaf(h4.w, w4.w, acc[r]);
            }
        }
        const float bb = fc2_b[c];
#pragma unroll
        for (int r = 0; r < 8; r++)
            sh2[(rbase + r) * 64 + c] = acc[r] + bb;
    }
    __syncthreads();

    // ---- stage 3: out[r][c] = h2[r] . fc3_w[c] + fc3_b[c] ----
    for (int idx = t; idx < 160; idx += 128) {
        const int r = idx / 10, c = idx % 10;
        float a = sb3[c];
        const float* h = sh2 + r * 64;
        const float* w = sw3 + c * 64;
#pragma unroll
        for (int k = 0; k < 64; k++) a = fmaf(h[k], w[k], a);
        out[(r0 + r) * 10 + c] = a;
    }
}

// ---------------------------------------------------------------------------
extern "C" void kernel_launch(void* const* d_in, const int* in_sizes, int n_in,
                              void* d_out, int out_size) {
    const float* x       = (const float*)d_in[0];
    const float* conv1_w = (const float*)d_in[1];
    const float* conv1_b = (const float*)d_in[2];
    const float* conv2_w = (const float*)d_in[3];
    const float* conv2_b = (const float*)d_in[4];
    const float* fc_w    = (const float*)d_in[5];
    const float* fc_b    = (const float*)d_in[6];
    const float* fc2_w   = (const float*)d_in[7];
    const float* fc2_b   = (const float*)d_in[8];
    const float* fc3_w   = (const float*)d_in[9];
    const float* fc3_b   = (const float*)d_in[10];
    float* out = (float*)d_out;

    const int B = in_sizes[0] / 784;

    k1_conv1<<<B, 192>>>(x, conv1_w, conv1_b);
    k2_conv2<<<B, 400>>>(conv2_w, conv2_b);
    k3_fc<<<B / 16, 128>>>(fc_w, fc_b, fc2_w, fc2_b, fc3_w, fc3_b, out);
}

// round 2
// speedup vs baseline: 1.5142x; 1.5142x over previous
#include <cuda_runtime.h>

#define BMAX 16384

// Padded conv1 output: per image 8 channels * 184 floats (13 rows * stride14, pad to 184)
// img stride = 8*184 = 1472 (multiple of 4 -> float4 staging OK)
__device__ float g_y1[BMAX * 1472];
__device__ float g_y2[BMAX * 400];   // conv2+pool, flattened (C,H,W)

// ---------------------------------------------------------------------------
// Kernel 1: conv1(3x3,1->8)+bias+relu+maxpool2 -> padded [8][13(x14 stride)]
// 3 images per block, 512 threads (507 active compute threads).
// ---------------------------------------------------------------------------
__global__ void __launch_bounds__(512) k1_conv1(const float* __restrict__ x,
                                                const float* __restrict__ w,
                                                const float* __restrict__ b,
                                                int B) {
    __shared__ float sx[3 * 784];
    __shared__ float sw[72];
    __shared__ float sb[8];
    const int img0 = blockIdx.x * 3;
    const int nimg = min(3, B - img0);
    const int t = threadIdx.x;
    for (int i = t; i < nimg * 784; i += 512) sx[i] = x[img0 * 784 + i];
    if (t < 72) sw[t] = w[t];
    if (t < 8)  sb[t] = b[t];
    __syncthreads();

    if (t >= 507) return;
    const int sub = t / 169;
    if (sub >= nimg) return;
    const int local = t - sub * 169;
    const int py = local / 13, px = local - py * 13;
    const float* xim = sx + sub * 784;

    float win[4][4];
#pragma unroll
    for (int i = 0; i < 4; i++)
#pragma unroll
        for (int j = 0; j < 4; j++)
            win[i][j] = xim[(2 * py + i) * 28 + (2 * px + j)];

    float* out = g_y1 + (img0 + sub) * 1472 + py * 14 + px;
#pragma unroll
    for (int oc = 0; oc < 8; oc++) {
        float c00 = 0.f, c01 = 0.f, c10 = 0.f, c11 = 0.f;
#pragma unroll
        for (int ky = 0; ky < 3; ky++)
#pragma unroll
            for (int kx = 0; kx < 3; kx++) {
                const float wv = sw[oc * 9 + ky * 3 + kx];
                c00 = fmaf(win[ky][kx],         wv, c00);
                c01 = fmaf(win[ky][kx + 1],     wv, c01);
                c10 = fmaf(win[ky + 1][kx],     wv, c10);
                c11 = fmaf(win[ky + 1][kx + 1], wv, c11);
            }
        float m = fmaxf(fmaxf(c00, c01), fmaxf(c10, c11)) + sb[oc];
        out[oc * 184] = fmaxf(m, 0.f);
    }
}

// ---------------------------------------------------------------------------
// Kernel 2: conv2(3x3,8->16)+bias+relu+maxpool2 -> [B,400]
// 4 images per block, 320 threads. Thread = (img, py, oc): all 5 px positions.
// Per ic: 4 rows loaded as float2 (24 LDS) + 9 weights, 180 FMAs.
// ---------------------------------------------------------------------------
__global__ void __launch_bounds__(320) k2_conv2(const float* __restrict__ w,
                                                const float* __restrict__ b) {
    __shared__ __align__(16) float sin_[4 * 1472];  // 23.5 KB
    __shared__ float sw[16 * 81];                   // padded: oc stride 81
    __shared__ float sb[16];
    const int img0 = blockIdx.x * 4;
    const int t = threadIdx.x;

    const float4* src = (const float4*)(g_y1 + img0 * 1472);
    for (int i = t; i < 1472; i += 320) ((float4*)sin_)[i] = src[i];
    for (int i = t; i < 1152; i += 320) {
        int oc = i / 72, rem = i - oc * 72;
        sw[oc * 81 + rem] = w[i];
    }
    if (t < 16) sb[t] = b[t];
    __syncthreads();

    const int sub = t / 80;          // image within block
    const int r = t - sub * 80;      // py*16 + oc
    const int py = r >> 4, oc = r & 15;
    const float* base = sin_ + sub * 1472 + (2 * py) * 14;

    float acc0[10], acc1[10];
#pragma unroll
    for (int c = 0; c < 10; c++) { acc0[c] = 0.f; acc1[c] = 0.f; }

#pragma unroll 2
    for (int ic = 0; ic < 8; ic++) {
        float wr[9];
        const float* wp = sw + oc * 81 + ic * 9;
#pragma unroll
        for (int k = 0; k < 9; k++) wr[k] = wp[k];
        const float* rows = base + ic * 184;
#pragma unroll
        for (int j = 0; j < 4; j++) {
            float row[12];
            const float2* rp = (const float2*)(rows + j * 14);
#pragma unroll
            for (int m = 0; m < 6; m++) {
                float2 v = rp[m];
                row[2 * m] = v.x; row[2 * m + 1] = v.y;
            }
            if (j < 3) {
#pragma unroll
                for (int c = 0; c < 10; c++) {
                    acc0[c] = fmaf(row[c],     wr[j * 3],     acc0[c]);
                    acc0[c] = fmaf(row[c + 1], wr[j * 3 + 1], acc0[c]);
                    acc0[c] = fmaf(row[c + 2], wr[j * 3 + 2], acc0[c]);
                }
            }
            if (j >= 1) {
                const int jj = j - 1;
#pragma unroll
                for (int c = 0; c < 10; c++) {
                    acc1[c] = fmaf(row[c],     wr[jj * 3],     acc1[c]);
                    acc1[c] = fmaf(row[c + 1], wr[jj * 3 + 1], acc1[c]);
                    acc1[c] = fmaf(row[c + 2], wr[jj * 3 + 2], acc1[c]);
                }
            }
        }
    }

    float* outp = g_y2 + (img0 + sub) * 400 + oc * 25 + py * 5;
    const float bb = sb[oc];
#pragma unroll
    for (int px = 0; px < 5; px++) {
        float m = fmaxf(fmaxf(acc0[2 * px], acc0[2 * px + 1]),
                        fmaxf(acc1[2 * px], acc1[2 * px + 1]));
        outp[px] = fmaxf(m + bb, 0.f);
    }
}

// ---------------------------------------------------------------------------
// Kernel 3: fc1(400->128)+relu, fc2(128->64), fc3(64->10), 16 rows per block.
// ---------------------------------------------------------------------------
__global__ void __launch_bounds__(128) k3_fc(const float* __restrict__ fc_w,
                                             const float* __restrict__ fc_b,
                                             const float* __restrict__ fc2_w,
                                             const float* __restrict__ fc2_b,
                                             const float* __restrict__ fc3_w,
                                             const float* __restrict__ fc3_b,
                                             float* __restrict__ out) {
    __shared__ float4 sx[16 * 100];   // 25.6 KB : X tile [16][400]
    __shared__ float4 sh1[16 * 32];   //  8.0 KB : h1 tile [16][128]
    __shared__ float  sh2[16 * 64];   //  4.0 KB : h2 tile [16][64]
    __shared__ float  sw3[640];
    __shared__ float  sb3[10];

    const int r0 = blockIdx.x * 16;
    const int t = threadIdx.x;

    const float4* xin = (const float4*)(g_y2 + r0 * 400);
    for (int i = t; i < 1600; i += 128) sx[i] = xin[i];
    for (int i = t; i < 640; i += 128) sw3[i] = fc3_w[i];
    if (t < 10) sb3[t] = fc3_b[t];
    __syncthreads();

    // ---- stage 1: h1[r][t] = relu(X[r] . fc_w[t] + fc_b[t]) ----
    {
        float acc[16];
#pragma unroll
        for (int r = 0; r < 16; r++) acc[r] = 0.f;
        const float4* wp = (const float4*)(fc_w + t * 400);
#pragma unroll 2
        for (int k4 = 0; k4 < 100; k4++) {
            const float4 w4 = wp[k4];
#pragma unroll
            for (int r = 0; r < 16; r++) {
                const float4 x4 = sx[r * 100 + k4];
                acc[r] = fmaf(x4.x, w4.x, acc[r]);
                acc[r] = fmaf(x4.y, w4.y, acc[r]);
                acc[r] = fmaf(x4.z, w4.z, acc[r]);
                acc[r] = fmaf(x4.w, w4.w, acc[r]);
            }
        }
        const float bb = fc_b[t];
        float* h1f = (float*)sh1;
#pragma unroll
        for (int r = 0; r < 16; r++)
            h1f[r * 128 + t] = fmaxf(acc[r] + bb, 0.f);
    }
    __syncthreads();

    // ---- stage 2: h2[r][c] = h1[r] . fc2_w[c] + fc2_b[c] ----
    {
        const int c = t & 63;
        const int rbase = (t >> 6) * 8;
        float acc[8];
#pragma unroll
        for (int r = 0; r < 8; r++) acc[r] = 0.f;
        const float4* wp = (const float4*)(fc2_w + c * 128);
#pragma unroll 4
        for (int k4 = 0; k4 < 32; k4++) {
            const float4 w4 = wp[k4];
#pragma unroll
            for (int r = 0; r < 8; r++) {
                const float4 h4 = sh1[(rbase + r) * 32 + k4];
                acc[r] = fmaf(h4.x, w4.x, acc[r]);
                acc[r] = fmaf(h4.y, w4.y, acc[r]);
                acc[r] = fmaf(h4.z, w4.z, acc[r]);
                acc[r] = fmaf(h4.w, w4.w, acc[r]);
            }
        }
        const float bb = fc2_b[c];
#pragma unroll
        for (int r = 0; r < 8; r++)
            sh2[(rbase + r) * 64 + c] = acc[r] + bb;
    }
    __syncthreads();

    // ---- stage 3: out[r][c] = h2[r] . fc3_w[c] + fc3_b[c] ----
    for (int idx = t; idx < 160; idx += 128) {
        const int r = idx / 10, c = idx % 10;
        float a = sb3[c];
        const float* h = sh2 + r * 64;
        const float* wv = sw3 + c * 64;
#pragma unroll
        for (int k = 0; k < 64; k++) a = fmaf(h[k], wv[k], a);
        out[(r0 + r) * 10 + c] = a;
    }
}

// ---------------------------------------------------------------------------
extern "C" void kernel_launch(void* const* d_in, const int* in_sizes, int n_in,
                              void* d_out, int out_size) {
    const float* x       = (const float*)d_in[0];
    const float* conv1_w = (const float*)d_in[1];
    const float* conv1_b = (const float*)d_in[2];
    const float* conv2_w = (const float*)d_in[3];
    const float* conv2_b = (const float*)d_in[4];
    const float* fc_w    = (const float*)d_in[5];
    const float* fc_b    = (const float*)d_in[6];
    const float* fc2_w   = (const float*)d_in[7];
    const float* fc2_b   = (const float*)d_in[8];
    const float* fc3_w   = (const float*)d_in[9];
    const float* fc3_b   = (const float*)d_in[10];
    float* out = (float*)d_out;

    const int B = in_sizes[0] / 784;

    k1_conv1<<<(B + 2) / 3, 512>>>(x, conv1_w, conv1_b, B);
    k2_conv2<<<B / 4, 320>>>(conv2_w, conv2_b);
    k3_fc<<<B / 16, 128>>>(fc_w, fc_b, fc2_w, fc2_b, fc3_w, fc3_b, out);
}